// round 11
// baseline (speedup 1.0000x reference)
#include <cuda_runtime.h>
#include <cuda_fp16.h>
#include <cstdint>

#define NMAX 200000
#define GMAX 64

// ---------------- scratch (device-code references ONLY) ----------------------
__device__ __align__(16) uint4  g_h1h[NMAX];   // 8 x fp16 (6 used): UNscaled x@W1
__device__ __align__(16) uint4  g_u1h[NMAX];   // 8 x fp16: dis*h1 (message)
__device__ __align__(16) uint4  g_a1h[NMAX];   // fp16 accumulator, init = self term
__device__ __align__(16) uint4  g_u2h[NMAX];   // 8 x fp16: dis*relu(layer1)
__device__ __align__(8)  float2 g_db[NMAX];    // (dis, batch-as-float-bits)
__device__ int   g_deg[NMAX];
__device__ float g_dis[NMAX];
__device__ float g_pool[GMAX * 6];
__device__ float g_cnt[GMAX];

// ---------------- helpers ------------------------------------------------------
__device__ __forceinline__ void red2f(float* p, float a, float b) {
    asm volatile("red.global.add.v2.f32 [%0], {%1,%2};"
                 :: "l"(p), "f"(a), "f"(b) : "memory");
}
__device__ __forceinline__ void red16h(uint4* p, uint4 m) {
    asm volatile("red.global.add.noftz.v4.f16x2 [%0], {%1,%2,%3,%4};"
                 :: "l"(p), "r"(m.x), "r"(m.y), "r"(m.z), "r"(m.w) : "memory");
}
__device__ __forceinline__ uint32_t pack2(float a, float b) {
    __half2 h = __floats2half2_rn(a, b);
    return *(uint32_t*)&h;
}
__device__ __forceinline__ float2 up2(uint32_t w) {
    return __half22float2(*(__half2*)&w);
}

// ---------------- K0: init ------------------------------------------------------
__global__ void kInit(int N) {
    int i = blockIdx.x * blockDim.x + threadIdx.x;
    if (i < N)        g_deg[i]  = 0;
    if (i < GMAX * 6) g_pool[i] = 0.f;
    if (i < GMAX)     g_cnt[i]  = 0.f;
}

// ---------------- K1: fused deg-count + H1 matmul (interleaved roles) -----------
#define H1_NODES 32
__global__ void __launch_bounds__(128) kFused(const float* __restrict__ x,
                                              const int* __restrict__ col,
                                              const float* __restrict__ W1,
                                              int N, int E, int HB, int R) {
    __shared__ float sx[H1_NODES * 132];
    __shared__ float sW[768];
    int bid = blockIdx.x;
    int q = bid / R, r = bid % R;
    bool isH1 = (r == R - 1) && (q < HB);

    if (!isH1) {
        int h1Before = q + ((r == R - 1) ? 1 : 0);
        if (h1Before > HB) h1Before = HB;
        int eb = bid - h1Before;
        int e = eb * 128 + threadIdx.x;
        if (e < E) atomicAdd(&g_deg[__ldg(col + e)], 1);
        return;
    }

    const int tid = threadIdx.x;
    for (int i = tid; i < 768; i += 128) sW[i] = W1[i];
    const int base = q * H1_NODES;
#pragma unroll
    for (int it = 0; it < 8; it++) {
        int f = tid + 128 * it;
        int node = f >> 5, c = f & 31;
        int gn = base + node;
        float4 v = make_float4(0.f, 0.f, 0.f, 0.f);
        if (gn < N) v = *(const float4*)(x + (size_t)gn * 128 + c * 4);
        *(float4*)&sx[node * 132 + c * 4] = v;
    }
    __syncthreads();

    int node = tid >> 2, sub = tid & 3;
    int gn = base + node;
    float a0 = 0.f, a1 = 0.f, a2 = 0.f, a3 = 0.f, a4 = 0.f, a5 = 0.f;
#pragma unroll
    for (int c = sub; c < 32; c += 4) {
        float4 xv = *(const float4*)&sx[node * 132 + c * 4];
        const float4* wp = (const float4*)&sW[c * 24];
        float4 w0 = wp[0], w1 = wp[1], w2 = wp[2], w3 = wp[3], w4 = wp[4], w5 = wp[5];
        a0 += xv.x * w0.x + xv.y * w1.z + xv.z * w3.x + xv.w * w4.z;
        a1 += xv.x * w0.y + xv.y * w1.w + xv.z * w3.y + xv.w * w4.w;
        a2 += xv.x * w0.z + xv.y * w2.x + xv.z * w3.z + xv.w * w5.x;
        a3 += xv.x * w0.w + xv.y * w2.y + xv.z * w3.w + xv.w * w5.y;
        a4 += xv.x * w1.x + xv.y * w2.z + xv.z * w4.x + xv.w * w5.z;
        a5 += xv.x * w1.y + xv.y * w2.w + xv.z * w4.y + xv.w * w5.w;
    }
#pragma unroll
    for (int o = 2; o; o >>= 1) {
        a0 += __shfl_xor_sync(0xffffffffu, a0, o, 4);
        a1 += __shfl_xor_sync(0xffffffffu, a1, o, 4);
        a2 += __shfl_xor_sync(0xffffffffu, a2, o, 4);
        a3 += __shfl_xor_sync(0xffffffffu, a3, o, 4);
        a4 += __shfl_xor_sync(0xffffffffu, a4, o, 4);
        a5 += __shfl_xor_sync(0xffffffffu, a5, o, 4);
    }
    if (sub == 0 && gn < N) {
        uint4 m;
        m.x = pack2(a0, a1);
        m.y = pack2(a2, a3);
        m.z = pack2(a4, a5);
        m.w = 0u;
        g_h1h[gn] = m;
    }
}

// ---------------- K2: dis, db=(dis,batch), u1 = dis*h1, a1 = u1 ------------------
__global__ void kU1(const int* __restrict__ batch, int N) {
    int i = blockIdx.x * blockDim.x + threadIdx.x;
    if (i >= N) return;
    float d = rsqrtf((float)(g_deg[i] + 1));
    g_dis[i] = d;
    float2 db;
    db.x = d;
    db.y = __int_as_float(__ldg(batch + i));
    g_db[i] = db;
    uint4 h = g_h1h[i];
    float2 s0 = up2(h.x), s1 = up2(h.y), s2 = up2(h.z);
    uint4 m;
    m.x = pack2(d * s0.x, d * s0.y);
    m.y = pack2(d * s1.x, d * s1.y);
    m.z = pack2(d * s2.x, d * s2.y);
    m.w = 0u;
    g_u1h[i] = m;
    g_a1h[i] = m;
}

// ---------------- K3: edge pass layer1 — 1 gather + 1 vector red -----------------
__global__ void kEdge1(const int* __restrict__ ei, int E) {
    int t = blockIdx.x * blockDim.x + threadIdx.x;
    if (t >= E) return;
    int r = __ldg(ei + t), c = __ldg(ei + E + t);
    uint4 m = g_u1h[r];
    red16h(&g_a1h[c], m);
}

// ---------------- K4: u2 = pack(dis*relu(dis*a1+b1)); self-term + cnt -> pool ----
__global__ void kMid(const float* __restrict__ b1, int N) {
    __shared__ float sb[6];
    if (threadIdx.x < 6) sb[threadIdx.x] = b1[threadIdx.x];
    __syncthreads();
    int i = blockIdx.x * blockDim.x + threadIdx.x;

    float v[6];
    float cn = 0.f;
    int g = -1;
    if (i < N) {
        float d = g_dis[i];
        uint4 a = g_a1h[i];
        float2 s0 = up2(a.x), s1 = up2(a.y), s2 = up2(a.z);
        float r0 = fmaxf(d * s0.x + sb[0], 0.f);
        float r1 = fmaxf(d * s0.y + sb[1], 0.f);
        float r2 = fmaxf(d * s1.x + sb[2], 0.f);
        float r3 = fmaxf(d * s1.y + sb[3], 0.f);
        float r4 = fmaxf(d * s2.x + sb[4], 0.f);
        float r5 = fmaxf(d * s2.y + sb[5], 0.f);
        uint4 w;
        w.x = pack2(d * r0, d * r1);
        w.y = pack2(d * r2, d * r3);
        w.z = pack2(d * r4, d * r5);
        w.w = 0u;
        g_u2h[i] = w;
        // self-term of layer-2 GCN, pre-pooled: dis * u2 = d^2 * relu(...)
        float dd = d * d;
        v[0] = dd * r0; v[1] = dd * r1; v[2] = dd * r2;
        v[3] = dd * r3; v[4] = dd * r4; v[5] = dd * r5;
        g = __float_as_int(g_db[i].y);
        cn = 1.f;
    } else {
#pragma unroll
        for (int j = 0; j < 6; j++) v[j] = 0.f;
    }

    int g0 = __shfl_sync(0xffffffffu, g, 0);
    bool uni = __all_sync(0xffffffffu, g == g0) && (g0 >= 0);
    if (uni) {
#pragma unroll
        for (int j = 0; j < 6; j++) {
#pragma unroll
            for (int o = 16; o; o >>= 1) v[j] += __shfl_xor_sync(0xffffffffu, v[j], o);
        }
#pragma unroll
        for (int o = 16; o; o >>= 1) cn += __shfl_xor_sync(0xffffffffu, cn, o);
        if ((threadIdx.x & 31) == 0) {
            float* dst = g_pool + g0 * 6;
            red2f(dst,     v[0], v[1]);
            red2f(dst + 2, v[2], v[3]);
            red2f(dst + 4, v[4], v[5]);
            atomicAdd(&g_cnt[g0], cn);
        }
    } else if (g >= 0) {
#pragma unroll
        for (int j = 0; j < 6; j++) atomicAdd(&g_pool[g * 6 + j], v[j]);
        atomicAdd(&g_cnt[g], 1.f);
    }
}

// ---------------- K5: edge pass layer2 fused with pooling ------------------------
// Per edge: gather u2[r] (16B) + (dis,batch)[c] (8B), accumulate into SMEM pool.
__global__ void __launch_bounds__(256) kEdge2Pool(const int* __restrict__ ei, int E) {
    __shared__ float sp[GMAX * 6];
    for (int i = threadIdx.x; i < GMAX * 6; i += 256) sp[i] = 0.f;
    __syncthreads();

    int stride = gridDim.x * 256;
    for (int t = blockIdx.x * 256 + threadIdx.x; t < E; t += stride) {
        int r = __ldg(ei + t), c = __ldg(ei + E + t);
        uint4 m = g_u2h[r];
        float2 db = g_db[c];
        float d = db.x;
        int g = __float_as_int(db.y);
        float2 s0 = up2(m.x), s1 = up2(m.y), s2 = up2(m.z);
        float* base = sp + g * 6;
        atomicAdd(base + 0, d * s0.x);
        atomicAdd(base + 1, d * s0.y);
        atomicAdd(base + 2, d * s1.x);
        atomicAdd(base + 3, d * s1.y);
        atomicAdd(base + 4, d * s2.x);
        atomicAdd(base + 5, d * s2.y);
    }
    __syncthreads();
    for (int i = threadIdx.x; i < GMAX * 6; i += 256) {
        float v = sp[i];
        if (v != 0.f) atomicAdd(&g_pool[i], v);
    }
}

// ---------------- K6: out = log_softmax((pool/cnt)@W2 + b2) ----------------------
__global__ void kOut(const float* __restrict__ W2, const float* __restrict__ b2,
                     float* __restrict__ out, int G) {
    __shared__ float sW[60];
    __shared__ float sb[10];
    if (threadIdx.x < 60) sW[threadIdx.x] = W2[threadIdx.x];
    if (threadIdx.x < 10) sb[threadIdx.x] = b2[threadIdx.x];
    __syncthreads();
    int g = threadIdx.x;
    if (g >= G) return;
    float c = fmaxf(g_cnt[g], 1.f);
    float p[6];
#pragma unroll
    for (int k = 0; k < 6; k++) p[k] = g_pool[g * 6 + k] / c;
    float v[10], m = -1e30f;
#pragma unroll
    for (int j = 0; j < 10; j++) {
        float s = sb[j];
#pragma unroll
        for (int k = 0; k < 6; k++) s += p[k] * sW[k * 10 + j];
        v[j] = s;
        m = fmaxf(m, s);
    }
    float s = 0.f;
#pragma unroll
    for (int j = 0; j < 10; j++) s += expf(v[j] - m);
    float l = m + logf(s);
#pragma unroll
    for (int j = 0; j < 10; j++) out[g * 10 + j] = v[j] - l;
}

// ---------------- launch -----------------------------------------------------------
extern "C" void kernel_launch(void* const* d_in, const int* in_sizes, int n_in,
                              void* d_out, int out_size) {
    const float* x     = (const float*)d_in[0];
    const int*   ei    = (const int*)d_in[1];
    const int*   batch = (const int*)d_in[2];
    const float* W1    = (const float*)d_in[3];
    const float* b1    = (const float*)d_in[4];
    const float* W2    = (const float*)d_in[5];
    const float* b2    = (const float*)d_in[6];

    int N = in_sizes[2];
    int E = in_sizes[1] / 2;
    int G = out_size / 10;
    if (N > NMAX) N = NMAX;

    int nb = (N + 255) / 256;
    int eb = (E + 255) / 256;

    int DB = (E + 127) / 128;
    int HB = (N + H1_NODES - 1) / H1_NODES;
    int grid = DB + HB;
    int R = grid / HB;

    kInit     <<<nb, 256>>>(N);
    kFused    <<<grid, 128>>>(x, ei + E, W1, N, E, HB, R);
    kU1       <<<nb, 256>>>(batch, N);
    kEdge1    <<<eb, 256>>>(ei, E);
    kMid      <<<nb, 256>>>(b1, N);
    kEdge2Pool<<<1480, 256>>>(ei, E);
    kOut      <<<1, 64>>>(W2, b2, (float*)d_out, G);
}

// round 12
// speedup vs baseline: 1.5405x; 1.5405x over previous
#include <cuda_runtime.h>
#include <cuda_fp16.h>
#include <cstdint>

#define NMAX 200000
#define GMAX 64

// ---------------- scratch (device-code references ONLY) ----------------------
__device__ __align__(16) uint4 g_h1h[NMAX];   // 8 x fp16 (6 used): UNscaled x@W1
__device__ __align__(16) uint4 g_u1h[NMAX];   // 8 x fp16: dis*h1 (message)
__device__ __align__(16) uint4 g_a1h[NMAX];   // fp16 accumulator, init = self term
__device__ __align__(16) uint4 g_u2h[NMAX];   // 8 x fp16: dis*relu(layer1)
__device__ __align__(16) uint4 g_a2h[NMAX];   // fp16 accumulator, init = self term
__device__ int   g_deg[NMAX];
__device__ float g_dis[NMAX];
__device__ float g_pool[GMAX * 6];
__device__ float g_cnt[GMAX];

// ---------------- helpers ------------------------------------------------------
__device__ __forceinline__ void red2f(float* p, float a, float b) {
    asm volatile("red.global.add.v2.f32 [%0], {%1,%2};"
                 :: "l"(p), "f"(a), "f"(b) : "memory");
}
__device__ __forceinline__ void red16h(uint4* p, uint4 m) {
    asm volatile("red.global.add.noftz.v4.f16x2 [%0], {%1,%2,%3,%4};"
                 :: "l"(p), "r"(m.x), "r"(m.y), "r"(m.z), "r"(m.w) : "memory");
}
__device__ __forceinline__ uint32_t pack2(float a, float b) {
    __half2 h = __floats2half2_rn(a, b);
    return *(uint32_t*)&h;
}
__device__ __forceinline__ float2 up2(uint32_t w) {
    return __half22float2(*(__half2*)&w);
}

// ---------------- K0: init ------------------------------------------------------
__global__ void kInit(int N) {
    int i = blockIdx.x * blockDim.x + threadIdx.x;
    if (i < N)        g_deg[i]  = 0;
    if (i < GMAX * 6) g_pool[i] = 0.f;
    if (i < GMAX)     g_cnt[i]  = 0.f;
}

// ---------------- K1: fused deg-count + H1 matmul (interleaved roles) -----------
#define H1_NODES 32
__global__ void __launch_bounds__(128) kFused(const float* __restrict__ x,
                                              const int* __restrict__ col,
                                              const float* __restrict__ W1,
                                              int N, int E, int HB, int R) {
    __shared__ float sx[H1_NODES * 132];
    __shared__ float sW[768];
    int bid = blockIdx.x;
    int q = bid / R, r = bid % R;
    bool isH1 = (r == R - 1) && (q < HB);

    if (!isH1) {
        int h1Before = q + ((r == R - 1) ? 1 : 0);
        if (h1Before > HB) h1Before = HB;
        int eb = bid - h1Before;
        int e = eb * 128 + threadIdx.x;
        if (e < E) atomicAdd(&g_deg[__ldg(col + e)], 1);
        return;
    }

    const int tid = threadIdx.x;
    for (int i = tid; i < 768; i += 128) sW[i] = W1[i];
    const int base = q * H1_NODES;
#pragma unroll
    for (int it = 0; it < 8; it++) {
        int f = tid + 128 * it;
        int node = f >> 5, c = f & 31;
        int gn = base + node;
        float4 v = make_float4(0.f, 0.f, 0.f, 0.f);
        if (gn < N) v = __ldcs((const float4*)(x + (size_t)gn * 128 + c * 4));
        *(float4*)&sx[node * 132 + c * 4] = v;
    }
    __syncthreads();

    int node = tid >> 2, sub = tid & 3;
    int gn = base + node;
    float a0 = 0.f, a1 = 0.f, a2 = 0.f, a3 = 0.f, a4 = 0.f, a5 = 0.f;
#pragma unroll
    for (int c = sub; c < 32; c += 4) {
        float4 xv = *(const float4*)&sx[node * 132 + c * 4];
        const float4* wp = (const float4*)&sW[c * 24];
        float4 w0 = wp[0], w1 = wp[1], w2 = wp[2], w3 = wp[3], w4 = wp[4], w5 = wp[5];
        a0 += xv.x * w0.x + xv.y * w1.z + xv.z * w3.x + xv.w * w4.z;
        a1 += xv.x * w0.y + xv.y * w1.w + xv.z * w3.y + xv.w * w4.w;
        a2 += xv.x * w0.z + xv.y * w2.x + xv.z * w3.z + xv.w * w5.x;
        a3 += xv.x * w0.w + xv.y * w2.y + xv.z * w3.w + xv.w * w5.y;
        a4 += xv.x * w1.x + xv.y * w2.z + xv.z * w4.x + xv.w * w5.z;
        a5 += xv.x * w1.y + xv.y * w2.w + xv.z * w4.y + xv.w * w5.w;
    }
#pragma unroll
    for (int o = 2; o; o >>= 1) {
        a0 += __shfl_xor_sync(0xffffffffu, a0, o, 4);
        a1 += __shfl_xor_sync(0xffffffffu, a1, o, 4);
        a2 += __shfl_xor_sync(0xffffffffu, a2, o, 4);
        a3 += __shfl_xor_sync(0xffffffffu, a3, o, 4);
        a4 += __shfl_xor_sync(0xffffffffu, a4, o, 4);
        a5 += __shfl_xor_sync(0xffffffffu, a5, o, 4);
    }
    if (sub == 0 && gn < N) {
        uint4 m;
        m.x = pack2(a0, a1);
        m.y = pack2(a2, a3);
        m.z = pack2(a4, a5);
        m.w = 0u;
        g_h1h[gn] = m;
    }
}

// ---------------- K2: dis; u1 = dis*h1; a1 = u1 ----------------------------------
__global__ void kU1(int N) {
    int i = blockIdx.x * blockDim.x + threadIdx.x;
    if (i >= N) return;
    float d = rsqrtf((float)(g_deg[i] + 1));
    g_dis[i] = d;
    uint4 h = g_h1h[i];
    float2 s0 = up2(h.x), s1 = up2(h.y), s2 = up2(h.z);
    uint4 m;
    m.x = pack2(d * s0.x, d * s0.y);
    m.y = pack2(d * s1.x, d * s1.y);
    m.z = pack2(d * s2.x, d * s2.y);
    m.w = 0u;
    g_u1h[i] = m;
    g_a1h[i] = m;
}

// ---------------- K3/K5: edge pass — 2 edges/thread, int2 idx loads --------------
template<int LAYER>
__global__ void kEdge(const int* __restrict__ ei, int E) {
    int t = (blockIdx.x * blockDim.x + threadIdx.x) * 2;
    if (t >= E) return;
    const uint4* u = (LAYER == 1) ? g_u1h : g_u2h;
    uint4*       a = (LAYER == 1) ? g_a1h : g_a2h;
    if (t + 1 < E) {
        int2 rr = *(const int2*)(ei + t);
        int2 cc = *(const int2*)(ei + E + t);
        uint4 m0 = u[rr.x];
        uint4 m1 = u[rr.y];
        red16h(&a[cc.x], m0);
        red16h(&a[cc.y], m1);
    } else {
        int r = __ldg(ei + t), c = __ldg(ei + E + t);
        uint4 m = u[r];
        red16h(&a[c], m);
    }
}

// ---------------- K4: u2 = pack(dis*relu(dis*a1 + b1)); a2 = u2 -------------------
__global__ void kMid(const float* __restrict__ b1, int N) {
    __shared__ float sb[6];
    if (threadIdx.x < 6) sb[threadIdx.x] = b1[threadIdx.x];
    __syncthreads();
    int i = blockIdx.x * blockDim.x + threadIdx.x;
    if (i >= N) return;
    float d = g_dis[i];
    uint4 a = g_a1h[i];
    float2 s0 = up2(a.x), s1 = up2(a.y), s2 = up2(a.z);
    float r0 = fmaxf(d * s0.x + sb[0], 0.f);
    float r1 = fmaxf(d * s0.y + sb[1], 0.f);
    float r2 = fmaxf(d * s1.x + sb[2], 0.f);
    float r3 = fmaxf(d * s1.y + sb[3], 0.f);
    float r4 = fmaxf(d * s2.x + sb[4], 0.f);
    float r5 = fmaxf(d * s2.y + sb[5], 0.f);
    uint4 w;
    w.x = pack2(d * r0, d * r1);
    w.y = pack2(d * r2, d * r3);
    w.z = pack2(d * r4, d * r5);
    w.w = 0u;
    g_u2h[i] = w;
    g_a2h[i] = w;
}

// ---------------- K6: pool v = dis*a2 (batch sorted, warp-uniform path) ----------
__global__ void kPool(const int* __restrict__ batch, int N) {
    int i = blockIdx.x * blockDim.x + threadIdx.x;
    float v[6];
    float cn = 0.f;
    int g = -1;
    if (i < N) {
        g = batch[i];
        float d = g_dis[i];
        uint4 a = g_a2h[i];
        float2 s0 = up2(a.x), s1 = up2(a.y), s2 = up2(a.z);
        v[0] = d * s0.x; v[1] = d * s0.y;
        v[2] = d * s1.x; v[3] = d * s1.y;
        v[4] = d * s2.x; v[5] = d * s2.y;
        cn = 1.f;
    } else {
#pragma unroll
        for (int j = 0; j < 6; j++) v[j] = 0.f;
    }
    int g0 = __shfl_sync(0xffffffffu, g, 0);
    bool uni = __all_sync(0xffffffffu, g == g0) && (g0 >= 0);
    if (uni) {
#pragma unroll
        for (int j = 0; j < 6; j++) {
#pragma unroll
            for (int o = 16; o; o >>= 1) v[j] += __shfl_xor_sync(0xffffffffu, v[j], o);
        }
#pragma unroll
        for (int o = 16; o; o >>= 1) cn += __shfl_xor_sync(0xffffffffu, cn, o);
        if ((threadIdx.x & 31) == 0) {
            float* dst = g_pool + g0 * 6;
            red2f(dst,     v[0], v[1]);
            red2f(dst + 2, v[2], v[3]);
            red2f(dst + 4, v[4], v[5]);
            atomicAdd(&g_cnt[g0], cn);
        }
    } else if (g >= 0) {
#pragma unroll
        for (int j = 0; j < 6; j++) atomicAdd(&g_pool[g * 6 + j], v[j]);
        atomicAdd(&g_cnt[g], 1.f);
    }
}

// ---------------- K7: out = log_softmax((pool/cnt)@W2 + b2) ----------------------
__global__ void kOut(const float* __restrict__ W2, const float* __restrict__ b2,
                     float* __restrict__ out, int G) {
    __shared__ float sW[60];
    __shared__ float sb[10];
    if (threadIdx.x < 60) sW[threadIdx.x] = W2[threadIdx.x];
    if (threadIdx.x < 10) sb[threadIdx.x] = b2[threadIdx.x];
    __syncthreads();
    int g = threadIdx.x;
    if (g >= G) return;
    float c = fmaxf(g_cnt[g], 1.f);
    float p[6];
#pragma unroll
    for (int k = 0; k < 6; k++) p[k] = g_pool[g * 6 + k] / c;
    float v[10], m = -1e30f;
#pragma unroll
    for (int j = 0; j < 10; j++) {
        float s = sb[j];
#pragma unroll
        for (int k = 0; k < 6; k++) s += p[k] * sW[k * 10 + j];
        v[j] = s;
        m = fmaxf(m, s);
    }
    float s = 0.f;
#pragma unroll
    for (int j = 0; j < 10; j++) s += expf(v[j] - m);
    float l = m + logf(s);
#pragma unroll
    for (int j = 0; j < 10; j++) out[g * 10 + j] = v[j] - l;
}

// ---------------- launch -----------------------------------------------------------
extern "C" void kernel_launch(void* const* d_in, const int* in_sizes, int n_in,
                              void* d_out, int out_size) {
    const float* x     = (const float*)d_in[0];
    const int*   ei    = (const int*)d_in[1];
    const int*   batch = (const int*)d_in[2];
    const float* W1    = (const float*)d_in[3];
    const float* b1    = (const float*)d_in[4];
    const float* W2    = (const float*)d_in[5];
    const float* b2    = (const float*)d_in[6];

    int N = in_sizes[2];
    int E = in_sizes[1] / 2;
    int G = out_size / 10;
    if (N > NMAX) N = NMAX;

    int nb = (N + 255) / 256;
    int eb2 = ((E + 1) / 2 + 255) / 256;     // 2 edges per thread

    int DB = (E + 127) / 128;
    int HB = (N + H1_NODES - 1) / H1_NODES;
    int grid = DB + HB;
    int R = grid / HB;

    kInit    <<<nb, 256>>>(N);
    kFused   <<<grid, 128>>>(x, ei + E, W1, N, E, HB, R);
    kU1      <<<nb, 256>>>(N);
    kEdge<1> <<<eb2, 256>>>(ei, E);          // 4th launch -> ncu capture
    kMid     <<<nb, 256>>>(b1, N);
    kEdge<2> <<<eb2, 256>>>(ei, E);
    kPool    <<<nb, 256>>>(batch, N);
    kOut     <<<1, 64>>>(W2, b2, (float*)d_out, G);
}

// round 14
// speedup vs baseline: 1.5571x; 1.0108x over previous
#include <cuda_runtime.h>
#include <cuda_fp16.h>
#include <cstdint>

#define NMAX 200000
#define GMAX 64

// ---------------- scratch (device-code references ONLY; self-cleaning) --------
__device__ __align__(16) uint4 g_h1h[NMAX];   // 8 x fp16 (6 used): UNscaled x@W1
__device__ __align__(16) uint4 g_u1h[NMAX];   // 8 x fp16: dis*h1 (message)
__device__ __align__(16) uint4 g_a1h[NMAX];   // fp16 accumulator, init = self term
__device__ __align__(16) uint4 g_u2h[NMAX];   // 8 x fp16: dis*relu(layer1)
__device__ __align__(16) uint4 g_a2h[NMAX];   // fp16 accumulator, init = self term
__device__ int      g_deg[NMAX];              // zeroed by kU1 after use
__device__ float    g_dis[NMAX];
__device__ float    g_pool[GMAX * 6];         // zeroed by kPoolOut after use
__device__ float    g_cnt[GMAX];              // zeroed by kPoolOut after use
__device__ unsigned g_ctr;                    // zeroed by kPoolOut after use

// ---------------- helpers ------------------------------------------------------
__device__ __forceinline__ void red2f(float* p, float a, float b) {
    asm volatile("red.global.add.v2.f32 [%0], {%1,%2};"
                 :: "l"(p), "f"(a), "f"(b) : "memory");
}
__device__ __forceinline__ void red16h(uint4* p, uint4 m) {
    asm volatile("red.global.add.noftz.v4.f16x2 [%0], {%1,%2,%3,%4};"
                 :: "l"(p), "r"(m.x), "r"(m.y), "r"(m.z), "r"(m.w) : "memory");
}
__device__ __forceinline__ uint32_t pack2(float a, float b) {
    __half2 h = __floats2half2_rn(a, b);
    return *(uint32_t*)&h;
}
__device__ __forceinline__ float2 up2(uint32_t w) {
    return __half22float2(*(__half2*)&w);
}

// ---------------- K1: fused deg-count + H1 matmul (interleaved roles) -----------
#define H1_NODES 32
__global__ void __launch_bounds__(128) kFused(const float* __restrict__ x,
                                              const int* __restrict__ col,
                                              const float* __restrict__ W1,
                                              int N, int E, int HB, int DB) {
    __shared__ float sx[H1_NODES * 132];
    __shared__ float sW[768];
    int bid = blockIdx.x;
    int mn = (HB < DB) ? HB : DB;
    int T = 2 * mn;
    bool isH1;
    int idx;
    if (bid < T) { isH1 = ((bid & 1) == 0); idx = bid >> 1; }
    else         { idx = mn + (bid - T);    isH1 = (HB > DB); }

    const int tid = threadIdx.x;
    if (!isH1) {
        int base = idx * 1024;
        if (((E & 3) == 0) && base + 1024 <= E) {
            int4 a = *(const int4*)(col + base + tid * 4);
            int4 b = *(const int4*)(col + base + 512 + tid * 4);
            atomicAdd(&g_deg[a.x], 1); atomicAdd(&g_deg[a.y], 1);
            atomicAdd(&g_deg[a.z], 1); atomicAdd(&g_deg[a.w], 1);
            atomicAdd(&g_deg[b.x], 1); atomicAdd(&g_deg[b.y], 1);
            atomicAdd(&g_deg[b.z], 1); atomicAdd(&g_deg[b.w], 1);
        } else {
            for (int e = base + tid; e < E && e < base + 1024; e += 128)
                atomicAdd(&g_deg[__ldg(col + e)], 1);
        }
        return;
    }

    // ---- H1 tile ----
    for (int i = tid; i < 768; i += 128) sW[i] = W1[i];
    const int base = idx * H1_NODES;
#pragma unroll
    for (int it = 0; it < 8; it++) {
        int f = tid + 128 * it;
        int node = f >> 5, c = f & 31;
        int gn = base + node;
        float4 v = make_float4(0.f, 0.f, 0.f, 0.f);
        if (gn < N) v = __ldcs((const float4*)(x + (size_t)gn * 128 + c * 4));
        *(float4*)&sx[node * 132 + c * 4] = v;
    }
    __syncthreads();

    int node = tid >> 2, sub = tid & 3;
    int gn = base + node;
    float a0 = 0.f, a1 = 0.f, a2 = 0.f, a3 = 0.f, a4 = 0.f, a5 = 0.f;
#pragma unroll
    for (int c = sub; c < 32; c += 4) {
        float4 xv = *(const float4*)&sx[node * 132 + c * 4];
        const float4* wp = (const float4*)&sW[c * 24];
        float4 w0 = wp[0], w1 = wp[1], w2 = wp[2], w3 = wp[3], w4 = wp[4], w5 = wp[5];
        a0 += xv.x * w0.x + xv.y * w1.z + xv.z * w3.x + xv.w * w4.z;
        a1 += xv.x * w0.y + xv.y * w1.w + xv.z * w3.y + xv.w * w4.w;
        a2 += xv.x * w0.z + xv.y * w2.x + xv.z * w3.z + xv.w * w5.x;
        a3 += xv.x * w0.w + xv.y * w2.y + xv.z * w3.w + xv.w * w5.y;
        a4 += xv.x * w1.x + xv.y * w2.z + xv.z * w4.x + xv.w * w5.z;
        a5 += xv.x * w1.y + xv.y * w2.w + xv.z * w4.y + xv.w * w5.w;
    }
#pragma unroll
    for (int o = 2; o; o >>= 1) {
        a0 += __shfl_xor_sync(0xffffffffu, a0, o, 4);
        a1 += __shfl_xor_sync(0xffffffffu, a1, o, 4);
        a2 += __shfl_xor_sync(0xffffffffu, a2, o, 4);
        a3 += __shfl_xor_sync(0xffffffffu, a3, o, 4);
        a4 += __shfl_xor_sync(0xffffffffu, a4, o, 4);
        a5 += __shfl_xor_sync(0xffffffffu, a5, o, 4);
    }
    if (sub == 0 && gn < N) {
        uint4 m;
        m.x = pack2(a0, a1);
        m.y = pack2(a2, a3);
        m.z = pack2(a4, a5);
        m.w = 0u;
        g_h1h[gn] = m;
    }
}

// ---------------- K2: dis; u1 = dis*h1; a1 = u1; deg self-clean ------------------
__global__ void kU1(int N) {
    int i = blockIdx.x * blockDim.x + threadIdx.x;
    if (i >= N) return;
    float d = rsqrtf((float)(g_deg[i] + 1));
    g_deg[i] = 0;                              // self-clean for next replay
    g_dis[i] = d;
    uint4 h = g_h1h[i];
    float2 s0 = up2(h.x), s1 = up2(h.y), s2 = up2(h.z);
    uint4 m;
    m.x = pack2(d * s0.x, d * s0.y);
    m.y = pack2(d * s1.x, d * s1.y);
    m.z = pack2(d * s2.x, d * s2.y);
    m.w = 0u;
    g_u1h[i] = m;
    g_a1h[i] = m;
}

// ---------------- K3/K5: edge pass — 4 edges/thread, int4 idx loads --------------
template<int LAYER>
__global__ void kEdge(const int* __restrict__ ei, int E) {
    int t = (blockIdx.x * blockDim.x + threadIdx.x) * 4;
    if (t >= E) return;
    const uint4* u = (LAYER == 1) ? g_u1h : g_u2h;
    uint4*       a = (LAYER == 1) ? g_a1h : g_a2h;
    if (((E & 3) == 0) && t + 3 < E) {
        int4 rr = *(const int4*)(ei + t);
        int4 cc = *(const int4*)(ei + E + t);
        uint4 m0 = u[rr.x];
        uint4 m1 = u[rr.y];
        uint4 m2 = u[rr.z];
        uint4 m3 = u[rr.w];
        red16h(&a[cc.x], m0);
        red16h(&a[cc.y], m1);
        red16h(&a[cc.z], m2);
        red16h(&a[cc.w], m3);
    } else {
        for (int e = t; e < E && e < t + 4; e++) {
            int r = __ldg(ei + e), c = __ldg(ei + E + e);
            uint4 m = u[r];
            red16h(&a[c], m);
        }
    }
}

// ---------------- K4: u2 = pack(dis*relu(dis*a1 + b1)); a2 = u2 -------------------
__global__ void kMid(const float* __restrict__ b1, int N) {
    __shared__ float sb[6];
    if (threadIdx.x < 6) sb[threadIdx.x] = b1[threadIdx.x];
    __syncthreads();
    int i = blockIdx.x * blockDim.x + threadIdx.x;
    if (i >= N) return;
    float d = g_dis[i];
    uint4 a = g_a1h[i];
    float2 s0 = up2(a.x), s1 = up2(a.y), s2 = up2(a.z);
    float r0 = fmaxf(d * s0.x + sb[0], 0.f);
    float r1 = fmaxf(d * s0.y + sb[1], 0.f);
    float r2 = fmaxf(d * s1.x + sb[2], 0.f);
    float r3 = fmaxf(d * s1.y + sb[3], 0.f);
    float r4 = fmaxf(d * s2.x + sb[4], 0.f);
    float r5 = fmaxf(d * s2.y + sb[5], 0.f);
    uint4 w;
    w.x = pack2(d * r0, d * r1);
    w.y = pack2(d * r2, d * r3);
    w.z = pack2(d * r4, d * r5);
    w.w = 0u;
    g_u2h[i] = w;
    g_a2h[i] = w;
}

// ---------------- K6: pool + last-block log_softmax + FULL self-clean ------------
__global__ void __launch_bounds__(256) kPoolOut(const int* __restrict__ batch,
                                                const float* __restrict__ W2,
                                                const float* __restrict__ b2,
                                                float* __restrict__ out,
                                                int N, int G, int NB) {
    int i = blockIdx.x * blockDim.x + threadIdx.x;
    float v[6];
    float cn = 0.f;
    int g = -1;
    if (i < N) {
        g = batch[i];
        float d = g_dis[i];
        uint4 a = g_a2h[i];
        float2 s0 = up2(a.x), s1 = up2(a.y), s2 = up2(a.z);
        v[0] = d * s0.x; v[1] = d * s0.y;
        v[2] = d * s1.x; v[3] = d * s1.y;
        v[4] = d * s2.x; v[5] = d * s2.y;
        cn = 1.f;
    } else {
#pragma unroll
        for (int j = 0; j < 6; j++) v[j] = 0.f;
    }
    int g0 = __shfl_sync(0xffffffffu, g, 0);
    bool uni = __all_sync(0xffffffffu, g == g0) && (g0 >= 0);
    if (uni) {
#pragma unroll
        for (int j = 0; j < 6; j++) {
#pragma unroll
            for (int o = 16; o; o >>= 1) v[j] += __shfl_xor_sync(0xffffffffu, v[j], o);
        }
#pragma unroll
        for (int o = 16; o; o >>= 1) cn += __shfl_xor_sync(0xffffffffu, cn, o);
        if ((threadIdx.x & 31) == 0) {
            float* dst = g_pool + g0 * 6;
            red2f(dst,     v[0], v[1]);
            red2f(dst + 2, v[2], v[3]);
            red2f(dst + 4, v[4], v[5]);
            atomicAdd(&g_cnt[g0], cn);
        }
    } else if (g >= 0) {
#pragma unroll
        for (int j = 0; j < 6; j++) atomicAdd(&g_pool[g * 6 + j], v[j]);
        atomicAdd(&g_cnt[g], 1.f);
    }

    // ---- last-block finalization ----
    __threadfence();
    __shared__ bool isLast;
    if (threadIdx.x == 0) {
        unsigned prev = atomicAdd(&g_ctr, 1u);
        isLast = (prev == (unsigned)(NB - 1));
    }
    __syncthreads();
    if (!isLast) return;
    __threadfence();                       // acquire: all pools visible

    __shared__ float sW[60];
    __shared__ float sb[10];
    if (threadIdx.x < 60) sW[threadIdx.x] = W2[threadIdx.x];
    if (threadIdx.x < 10) sb[threadIdx.x] = b2[threadIdx.x];
    __syncthreads();
    int gg = threadIdx.x;
    if (gg < G) {
        float c = fmaxf(g_cnt[gg], 1.f);
        float p[6];
#pragma unroll
        for (int k = 0; k < 6; k++) p[k] = g_pool[gg * 6 + k] / c;
        float vv[10], m = -1e30f;
#pragma unroll
        for (int j = 0; j < 10; j++) {
            float s = sb[j];
#pragma unroll
            for (int k = 0; k < 6; k++) s += p[k] * sW[k * 10 + j];
            vv[j] = s;
            m = fmaxf(m, s);
        }
        float s = 0.f;
#pragma unroll
        for (int j = 0; j < 10; j++) s += expf(vv[j] - m);
        float l = m + logf(s);
#pragma unroll
        for (int j = 0; j < 10; j++) out[gg * 10 + j] = vv[j] - l;
    }
    __syncthreads();                       // outputs done before self-clean
    // FULL cleanup (FIX: stride loop covers all GMAX*6=384 entries, not just 256)
    for (int k = threadIdx.x; k < GMAX * 6; k += 256) g_pool[k] = 0.f;
    if (threadIdx.x < GMAX) g_cnt[threadIdx.x] = 0.f;
    if (threadIdx.x == 0)   g_ctr = 0u;
}

// ---------------- launch -----------------------------------------------------------
extern "C" void kernel_launch(void* const* d_in, const int* in_sizes, int n_in,
                              void* d_out, int out_size) {
    const float* x     = (const float*)d_in[0];
    const int*   ei    = (const int*)d_in[1];
    const int*   batch = (const int*)d_in[2];
    const float* W1    = (const float*)d_in[3];
    const float* b1    = (const float*)d_in[4];
    const float* W2    = (const float*)d_in[5];
    const float* b2    = (const float*)d_in[6];

    int N = in_sizes[2];
    int E = in_sizes[1] / 2;
    int G = out_size / 10;
    if (N > NMAX) N = NMAX;

    int nb  = (N + 255) / 256;
    int eb4 = ((E + 3) / 4 + 255) / 256;
    int HB  = (N + H1_NODES - 1) / H1_NODES;
    int DB  = (E + 1023) / 1024;

    kFused   <<<HB + DB, 128>>>(x, ei + E, W1, N, E, HB, DB);
    kU1      <<<nb, 256>>>(N);
    kEdge<1> <<<eb4, 256>>>(ei, E);
    kMid     <<<nb, 256>>>(b1, N);
    kEdge<2> <<<eb4, 256>>>(ei, E);
    kPoolOut <<<nb, 256>>>(batch, W2, b2, (float*)d_out, N, G, nb);
}